// round 1
// baseline (speedup 1.0000x reference)
#include <cuda_runtime.h>
#include <math.h>

#define MT 16384   // B*T
#define TT 4096
#define CC 512

// ---------------- scratch (device globals; no runtime allocation) ----------------
__device__ float g_h  [MT*CC];
__device__ float g_q0 [MT*CC];
__device__ float g_q1 [MT*CC];
__device__ float g_v  [MT*CC];
__device__ float g_zb [MT*CC];
__device__ float g_x1 [MT*CC];
__device__ float g_mlp[MT*2048];
__device__ float g_pA [2*CC*CC];
__device__ float g_pB [2*CC*CC];
__device__ float g_pY [2*CC*CC];
__device__ float g_pZ [2*CC*CC];
__device__ float g_n2 [2];

// ---------------- layernorm (one block per row, 128 threads) ----------------
__global__ void ln_kernel(const float* __restrict__ x, const float* __restrict__ w,
                          float* __restrict__ out) {
    int r = blockIdx.x;
    const float4* xr = (const float4*)(x + (size_t)r * CC);
    float4 v = xr[threadIdx.x];
    float s  = v.x + v.y + v.z + v.w;
    float s2 = v.x*v.x + v.y*v.y + v.z*v.z + v.w*v.w;
    __shared__ float sm[8];
    #pragma unroll
    for (int o = 16; o; o >>= 1) {
        s  += __shfl_down_sync(0xffffffffu, s,  o);
        s2 += __shfl_down_sync(0xffffffffu, s2, o);
    }
    if ((threadIdx.x & 31) == 0) { sm[threadIdx.x >> 5] = s; sm[(threadIdx.x >> 5) + 4] = s2; }
    __syncthreads();
    float S  = sm[0] + sm[1] + sm[2] + sm[3];
    float S2 = sm[4] + sm[5] + sm[6] + sm[7];
    float mean = S * (1.0f / CC);
    float var  = S2 * (1.0f / CC) - mean * mean;
    float rstd = rsqrtf(var + 1e-5f);
    float4 wv = ((const float4*)w)[threadIdx.x];
    float4 o;
    o.x = (v.x - mean) * rstd * wv.x;
    o.y = (v.y - mean) * rstd * wv.y;
    o.z = (v.z - mean) * rstd * wv.z;
    o.w = (v.w - mean) * rstd * wv.w;
    ((float4*)(out + (size_t)r * CC))[threadIdx.x] = o;
}

// ---------------- rmsnorm + frontier select for the scan ----------------
__global__ void rms_update(const float* __restrict__ z, const float* __restrict__ qin,
                           float* __restrict__ qout, int d) {
    int r = blockIdx.x;
    int t = r & (TT - 1);
    if (t >= d) {
        float4 v = ((const float4*)(z + (size_t)r * CC))[threadIdx.x];
        float s2 = v.x*v.x + v.y*v.y + v.z*v.z + v.w*v.w;
        __shared__ float sm[4];
        #pragma unroll
        for (int o = 16; o; o >>= 1) s2 += __shfl_down_sync(0xffffffffu, s2, o);
        if ((threadIdx.x & 31) == 0) sm[threadIdx.x >> 5] = s2;
        __syncthreads();
        float S2 = sm[0] + sm[1] + sm[2] + sm[3];
        float sc = rsqrtf(S2 * (1.0f / CC) + 1e-6f);
        float4 o; o.x = v.x*sc; o.y = v.y*sc; o.z = v.z*sc; o.w = v.w*sc;
        ((float4*)(qout + (size_t)r * CC))[threadIdx.x] = o;
    } else {
        ((float4*)(qout + (size_t)r * CC))[threadIdx.x] =
            ((const float4*)(qin + (size_t)r * CC))[threadIdx.x];
    }
}

__device__ __forceinline__ float gelu_exact(float v) {
    return 0.5f * v * (1.0f + erff(v * 0.7071067811865475f));
}

// ---------------- generic NT GEMM: C = A@B^T (+R) (gelu) (A:=A*A2) ----------------
// EPI bit0 = residual add R, bit1 = gelu, bit2 = A elementwise product with A2
template<int EPI>
__global__ void __launch_bounds__(256) gemm64(const float* __restrict__ A,
                                              const float* __restrict__ A2,
                                              const float* __restrict__ B,
                                              const float* __restrict__ R,
                                              float* __restrict__ C,
                                              int N, int K) {
    __shared__ float As[16][68], Bs[16][68];
    int m0 = blockIdx.y << 6, n0 = blockIdx.x << 6;
    int tid = threadIdx.x;
    int lr = tid >> 2, lk = (tid & 3) << 2;
    int ty = tid >> 4, tx = tid & 15;
    const float* Ap  = A + (size_t)(m0 + lr) * K + lk;
    const float* A2p = (EPI & 4) ? (A2 + (size_t)(m0 + lr) * K + lk) : A;
    const float* Bp  = B + (size_t)(n0 + lr) * K + lk;
    float acc[4][4];
    #pragma unroll
    for (int i = 0; i < 4; i++)
        #pragma unroll
        for (int j = 0; j < 4; j++) acc[i][j] = 0.0f;

    for (int k0 = 0; k0 < K; k0 += 16) {
        float4 a = *(const float4*)(Ap + k0);
        if (EPI & 4) {
            float4 a2 = *(const float4*)(A2p + k0);
            a.x *= a2.x; a.y *= a2.y; a.z *= a2.z; a.w *= a2.w;
        }
        float4 b = *(const float4*)(Bp + k0);
        As[lk+0][lr] = a.x; As[lk+1][lr] = a.y; As[lk+2][lr] = a.z; As[lk+3][lr] = a.w;
        Bs[lk+0][lr] = b.x; Bs[lk+1][lr] = b.y; Bs[lk+2][lr] = b.z; Bs[lk+3][lr] = b.w;
        __syncthreads();
        #pragma unroll
        for (int kk = 0; kk < 16; kk++) {
            float4 a4 = *(const float4*)(&As[kk][ty << 2]);
            float4 b4 = *(const float4*)(&Bs[kk][tx << 2]);
            float ar[4] = {a4.x, a4.y, a4.z, a4.w};
            float br[4] = {b4.x, b4.y, b4.z, b4.w};
            #pragma unroll
            for (int i = 0; i < 4; i++)
                #pragma unroll
                for (int j = 0; j < 4; j++)
                    acc[i][j] = fmaf(ar[i], br[j], acc[i][j]);
        }
        __syncthreads();
    }
    #pragma unroll
    for (int i = 0; i < 4; i++) {
        int row = m0 + (ty << 2) + i;
        float4 o; o.x = acc[i][0]; o.y = acc[i][1]; o.z = acc[i][2]; o.w = acc[i][3];
        if (EPI & 2) { o.x = gelu_exact(o.x); o.y = gelu_exact(o.y);
                       o.z = gelu_exact(o.z); o.w = gelu_exact(o.w); }
        if (EPI & 1) {
            float4 rv = *(const float4*)(R + (size_t)row * N + n0 + (tx << 2));
            o.x += rv.x; o.y += rv.y; o.z += rv.z; o.w += rv.w;
        }
        *(float4*)(C + (size_t)row * N + n0 + (tx << 2)) = o;
    }
}

// ---------------- scan dual-GEMM: z = left@P1^T + q@P2^T ----------------
__global__ void __launch_bounds__(256) gemm_scan(const float* __restrict__ q,
                                                 const float* __restrict__ P1,
                                                 const float* __restrict__ P2,
                                                 float* __restrict__ z, int d) {
    int m0 = blockIdx.y << 6, n0 = blockIdx.x << 6;
    int t0 = m0 & (TT - 1);
    if (t0 + 63 < d) return;  // whole block below frontier: rows just get copied later
    __shared__ float Al[16][68], Aq[16][68], B1[16][68], B2[16][68];
    int tid = threadIdx.x;
    int lr = tid >> 2, lk = (tid & 3) << 2;
    int ty = tid >> 4, tx = tid & 15;
    int r = m0 + lr;
    int t = r & (TT - 1);
    const float* aq = q + (size_t)r * CC + lk;
    const float* al = (t >= d) ? (aq - (size_t)d * CC) : aq;  // t<d rows are discarded later
    const float* b1 = P1 + (size_t)(n0 + lr) * CC + lk;
    const float* b2 = P2 + (size_t)(n0 + lr) * CC + lk;
    float acc[4][4];
    #pragma unroll
    for (int i = 0; i < 4; i++)
        #pragma unroll
        for (int j = 0; j < 4; j++) acc[i][j] = 0.0f;

    for (int k0 = 0; k0 < CC; k0 += 16) {
        float4 va = *(const float4*)(al + k0);
        float4 vq = *(const float4*)(aq + k0);
        float4 v1 = *(const float4*)(b1 + k0);
        float4 v2 = *(const float4*)(b2 + k0);
        Al[lk+0][lr] = va.x; Al[lk+1][lr] = va.y; Al[lk+2][lr] = va.z; Al[lk+3][lr] = va.w;
        Aq[lk+0][lr] = vq.x; Aq[lk+1][lr] = vq.y; Aq[lk+2][lr] = vq.z; Aq[lk+3][lr] = vq.w;
        B1[lk+0][lr] = v1.x; B1[lk+1][lr] = v1.y; B1[lk+2][lr] = v1.z; B1[lk+3][lr] = v1.w;
        B2[lk+0][lr] = v2.x; B2[lk+1][lr] = v2.y; B2[lk+2][lr] = v2.z; B2[lk+3][lr] = v2.w;
        __syncthreads();
        #pragma unroll
        for (int kk = 0; kk < 16; kk++) {
            float4 a4 = *(const float4*)(&Al[kk][ty << 2]);
            float4 q4 = *(const float4*)(&Aq[kk][ty << 2]);
            float4 x4 = *(const float4*)(&B1[kk][tx << 2]);
            float4 y4 = *(const float4*)(&B2[kk][tx << 2]);
            float ar[4] = {a4.x, a4.y, a4.z, a4.w};
            float qr[4] = {q4.x, q4.y, q4.z, q4.w};
            float b1r[4] = {x4.x, x4.y, x4.z, x4.w};
            float b2r[4] = {y4.x, y4.y, y4.z, y4.w};
            #pragma unroll
            for (int i = 0; i < 4; i++)
                #pragma unroll
                for (int j = 0; j < 4; j++) {
                    acc[i][j] = fmaf(ar[i], b1r[j], acc[i][j]);
                    acc[i][j] = fmaf(qr[i], b2r[j], acc[i][j]);
                }
        }
        __syncthreads();
    }
    #pragma unroll
    for (int i = 0; i < 4; i++) {
        int row = m0 + (ty << 2) + i;
        float4 o; o.x = acc[i][0]; o.y = acc[i][1]; o.z = acc[i][2]; o.w = acc[i][3];
        *(float4*)(z + (size_t)row * CC + n0 + (tx << 2)) = o;
    }
}

// ---------------- 512x512 small GEMM for polar iterations ----------------
// BT=true : C = alpha*(A@B^T) + beta*D     (NT)
// BT=false: C = alpha*(A@B)   + beta*D     (NN)
template<bool BT, bool AXPBY>
__global__ void __launch_bounds__(64) gemm512k(const float* __restrict__ A,
                                               const float* __restrict__ B,
                                               const float* __restrict__ D,
                                               float* __restrict__ C,
                                               float alpha, float beta) {
    size_t off = (size_t)blockIdx.z * CC * CC;
    A += off; B += off; C += off;
    if (AXPBY) D += off;
    int m0 = blockIdx.y << 5, n0 = blockIdx.x << 5;
    __shared__ float As[16][36], Bs[16][36];
    int tid = threadIdx.x;
    int ty = tid >> 3, tx = tid & 7;
    float acc[4][4];
    #pragma unroll
    for (int i = 0; i < 4; i++)
        #pragma unroll
        for (int j = 0; j < 4; j++) acc[i][j] = 0.0f;

    for (int k0 = 0; k0 < CC; k0 += 16) {
        #pragma unroll
        for (int u = 0; u < 2; u++) {
            int f = tid * 2 + u;
            int row = f >> 2, kq = (f & 3) << 2;
            float4 a = *(const float4*)(A + (size_t)(m0 + row) * CC + k0 + kq);
            As[kq+0][row] = a.x; As[kq+1][row] = a.y; As[kq+2][row] = a.z; As[kq+3][row] = a.w;
            if (BT) {
                float4 b = *(const float4*)(B + (size_t)(n0 + row) * CC + k0 + kq);
                Bs[kq+0][row] = b.x; Bs[kq+1][row] = b.y; Bs[kq+2][row] = b.z; Bs[kq+3][row] = b.w;
            } else {
                int krow = f >> 3, nf = f & 7;
                float4 b = *(const float4*)(B + (size_t)(k0 + krow) * CC + n0 + (nf << 2));
                *(float4*)(&Bs[krow][nf << 2]) = b;
            }
        }
        __syncthreads();
        #pragma unroll
        for (int kk = 0; kk < 16; kk++) {
            float4 a4 = *(const float4*)(&As[kk][ty << 2]);
            float4 b4 = *(const float4*)(&Bs[kk][tx << 2]);
            float ar[4] = {a4.x, a4.y, a4.z, a4.w};
            float br[4] = {b4.x, b4.y, b4.z, b4.w};
            #pragma unroll
            for (int i = 0; i < 4; i++)
                #pragma unroll
                for (int j = 0; j < 4; j++)
                    acc[i][j] = fmaf(ar[i], br[j], acc[i][j]);
        }
        __syncthreads();
    }
    #pragma unroll
    for (int i = 0; i < 4; i++) {
        int row = m0 + (ty << 2) + i;
        float4 o; o.x = acc[i][0]; o.y = acc[i][1]; o.z = acc[i][2]; o.w = acc[i][3];
        if (AXPBY) {
            float4 dv = *(const float4*)(D + (size_t)row * CC + n0 + (tx << 2));
            o.x = alpha * o.x + beta * dv.x;
            o.y = alpha * o.y + beta * dv.y;
            o.z = alpha * o.z + beta * dv.z;
            o.w = alpha * o.w + beta * dv.w;
        }
        *(float4*)(C + (size_t)row * CC + n0 + (tx << 2)) = o;
    }
}

// ---------------- polar init: Frobenius norm + scale ----------------
__global__ void fro_zero() { if (threadIdx.x < 2) g_n2[threadIdx.x] = 0.0f; }

__global__ void fro_reduce(const float* __restrict__ W1, const float* __restrict__ W2) {
    const float* W = blockIdx.y ? W2 : W1;
    int i = blockIdx.x * 256 + threadIdx.x;
    float s = 0.0f;
    for (int j = i; j < CC * CC; j += 64 * 256) { float v = W[j]; s += v * v; }
    #pragma unroll
    for (int o = 16; o; o >>= 1) s += __shfl_down_sync(0xffffffffu, s, o);
    __shared__ float sm[8];
    if ((threadIdx.x & 31) == 0) sm[threadIdx.x >> 5] = s;
    __syncthreads();
    if (threadIdx.x == 0) {
        float S = 0.0f;
        #pragma unroll
        for (int w = 0; w < 8; w++) S += sm[w];
        atomicAdd(&g_n2[blockIdx.y], S);
    }
}

__global__ void polar_init(const float* __restrict__ W1, const float* __restrict__ W2,
                           float* __restrict__ X) {
    int zb = blockIdx.y;
    const float* W = zb ? W2 : W1;
    float inv = rsqrtf(g_n2[zb]);
    int i = blockIdx.x * 256 + threadIdx.x;
    X[(size_t)zb * CC * CC + i] = W[i] * inv;
}

// ---------------- host orchestration ----------------
extern "C" void kernel_launch(void* const* d_in, const int* in_sizes, int n_in,
                              void* d_out, int out_size) {
    const float* x    = (const float*)d_in[0];
    const float* ln1w = (const float*)d_in[1];
    const float* Wq   = (const float*)d_in[2];
    const float* Wv   = (const float*)d_in[3];
    const float* Wo   = (const float*)d_in[4];
    // d_in[5] = identity : provably unused (pscan discards all rows that see it)
    const float* Wp1  = (const float*)d_in[6];
    const float* Wp2  = (const float*)d_in[7];
    const float* ln2w = (const float*)d_in[8];
    const float* Wfc  = (const float*)d_in[9];
    const float* Wpr  = (const float*)d_in[10];
    float* out = (float*)d_out;

    float *h, *q0, *q1, *v, *zb, *x1, *mlp, *pA, *pB, *pY, *pZ;
    cudaGetSymbolAddress((void**)&h,   g_h);
    cudaGetSymbolAddress((void**)&q0,  g_q0);
    cudaGetSymbolAddress((void**)&q1,  g_q1);
    cudaGetSymbolAddress((void**)&v,   g_v);
    cudaGetSymbolAddress((void**)&zb,  g_zb);
    cudaGetSymbolAddress((void**)&x1,  g_x1);
    cudaGetSymbolAddress((void**)&mlp, g_mlp);
    cudaGetSymbolAddress((void**)&pA,  g_pA);
    cudaGetSymbolAddress((void**)&pB,  g_pB);
    cudaGetSymbolAddress((void**)&pY,  g_pY);
    cudaGetSymbolAddress((void**)&pZ,  g_pZ);

    dim3 g8(8, 256), g32(32, 256);

    // --- SSM branch prologue ---
    ln_kernel<<<MT, 128>>>(x, ln1w, h);
    gemm64<0><<<g8, 256>>>(h, nullptr, Wq, nullptr, q0, 512, 512);
    gemm64<0><<<g8, 256>>>(h, nullptr, Wv, nullptr, v,  512, 512);

    // --- polar factors of Wp1, Wp2 via quintic + Newton-Schulz ---
    fro_zero<<<1, 32>>>();
    fro_reduce<<<dim3(64, 2), 256>>>(Wp1, Wp2);
    polar_init<<<dim3(1024, 2), 256>>>(Wp1, Wp2, pA);

    float* X  = pA;
    float* Xn = pB;
    dim3 gs(16, 16, 2);
    const float qa = 3.4445f, qb = -4.7750f, qc = 2.0315f;
    for (int it = 0; it < 12; it++) {
        gemm512k<true,  false><<<gs, 64>>>(X,  X,  nullptr, pY, 1.0f, 0.0f);  // Y = X X^T
        gemm512k<true,  true ><<<gs, 64>>>(pY, pY, pY,      pZ, qc,   qb);    // Z = c Y^2 + b Y
        gemm512k<false, true ><<<gs, 64>>>(pZ, X,  X,       Xn, 1.0f, qa);    // X' = Z X + a X
        float* t = X; X = Xn; Xn = t;
    }
    for (int it = 0; it < 6; it++) {
        gemm512k<true,  false><<<gs, 64>>>(X,  X, nullptr, pY, 1.0f,  0.0f);  // Y = X X^T
        gemm512k<false, true ><<<gs, 64>>>(pY, X, X,       Xn, -0.5f, 1.5f);  // X' = 1.5X - .5 Y X
        float* t = X; X = Xn; Xn = t;
    }
    const float* P1 = X;
    const float* P2 = X + CC * CC;

    // --- parallel scan: 12 levels ---
    float* qc_ = q0;
    float* qn_ = q1;
    for (int d = 1; d < TT; d <<= 1) {
        gemm_scan<<<g8, 256>>>(qc_, P1, P2, zb, d);
        rms_update<<<MT, 128>>>(zb, qc_, qn_, d);
        float* t = qc_; qc_ = qn_; qn_ = t;
    }

    // --- output projection: x1 = x + (q*v) @ Wo^T ---
    gemm64<5><<<g8, 256>>>(qc_, v, Wo, x, x1, 512, 512);

    // --- MLP branch ---
    ln_kernel<<<MT, 128>>>(x1, ln2w, h);
    gemm64<2><<<g32, 256>>>(h,   nullptr, Wfc, nullptr, mlp, 2048, 512);   // gelu(h @ Wfc^T)
    gemm64<1><<<g8,  256>>>(mlp, nullptr, Wpr, x1,      out, 512, 2048);   // out = x1 + mlp @ Wpr^T
}

// round 2
// speedup vs baseline: 1.0016x; 1.0016x over previous
#include <cuda_runtime.h>
#include <math.h>

#define MT 16384   // B*T
#define TT 4096
#define CC 512

// ---------------- scratch (device globals; no runtime allocation) ----------------
__device__ float g_h  [MT*CC];
__device__ float g_q0 [MT*CC];
__device__ float g_q1 [MT*CC];
__device__ float g_v  [MT*CC];
__device__ float g_zb [MT*CC];
__device__ float g_x1 [MT*CC];
__device__ float g_mlp[MT*2048];
__device__ float g_pA [2*CC*CC];
__device__ float g_pB [2*CC*CC];
__device__ float g_pY [2*CC*CC];
__device__ float g_pZ [2*CC*CC];
__device__ float g_n2 [2];

// ---------------- layernorm (one block per row, 128 threads) ----------------
__global__ void ln_kernel(const float* __restrict__ x, const float* __restrict__ w,
                          float* __restrict__ out) {
    int r = blockIdx.x;
    const float4* xr = (const float4*)(x + (size_t)r * CC);
    float4 v = xr[threadIdx.x];
    float s  = v.x + v.y + v.z + v.w;
    float s2 = v.x*v.x + v.y*v.y + v.z*v.z + v.w*v.w;
    __shared__ float sm[8];
    #pragma unroll
    for (int o = 16; o; o >>= 1) {
        s  += __shfl_down_sync(0xffffffffu, s,  o);
        s2 += __shfl_down_sync(0xffffffffu, s2, o);
    }
    if ((threadIdx.x & 31) == 0) { sm[threadIdx.x >> 5] = s; sm[(threadIdx.x >> 5) + 4] = s2; }
    __syncthreads();
    float S  = sm[0] + sm[1] + sm[2] + sm[3];
    float S2 = sm[4] + sm[5] + sm[6] + sm[7];
    float mean = S * (1.0f / CC);
    float var  = S2 * (1.0f / CC) - mean * mean;
    float rstd = rsqrtf(var + 1e-5f);
    float4 wv = ((const float4*)w)[threadIdx.x];
    float4 o;
    o.x = (v.x - mean) * rstd * wv.x;
    o.y = (v.y - mean) * rstd * wv.y;
    o.z = (v.z - mean) * rstd * wv.z;
    o.w = (v.w - mean) * rstd * wv.w;
    ((float4*)(out + (size_t)r * CC))[threadIdx.x] = o;
}

// ---------------- rmsnorm + frontier select for the scan ----------------
__global__ void rms_update(const float* __restrict__ z, const float* __restrict__ qin,
                           float* __restrict__ qout, int d) {
    int r = blockIdx.x;
    int t = r & (TT - 1);
    if (t >= d) {
        float4 v = ((const float4*)(z + (size_t)r * CC))[threadIdx.x];
        float s2 = v.x*v.x + v.y*v.y + v.z*v.z + v.w*v.w;
        __shared__ float sm[4];
        #pragma unroll
        for (int o = 16; o; o >>= 1) s2 += __shfl_down_sync(0xffffffffu, s2, o);
        if ((threadIdx.x & 31) == 0) sm[threadIdx.x >> 5] = s2;
        __syncthreads();
        float S2 = sm[0] + sm[1] + sm[2] + sm[3];
        float sc = rsqrtf(S2 * (1.0f / CC) + 1e-6f);
        float4 o; o.x = v.x*sc; o.y = v.y*sc; o.z = v.z*sc; o.w = v.w*sc;
        ((float4*)(qout + (size_t)r * CC))[threadIdx.x] = o;
    } else {
        ((float4*)(qout + (size_t)r * CC))[threadIdx.x] =
            ((const float4*)(qin + (size_t)r * CC))[threadIdx.x];
    }
}

__device__ __forceinline__ float gelu_exact(float v) {
    return 0.5f * v * (1.0f + erff(v * 0.7071067811865475f));
}

// ---------------- generic NT GEMM: C = A@B^T (+R) (gelu) (A:=A*A2) ----------------
// EPI bit0 = residual add R, bit1 = gelu, bit2 = A elementwise product with A2
template<int EPI>
__global__ void __launch_bounds__(256) gemm64(const float* __restrict__ A,
                                              const float* __restrict__ A2,
                                              const float* __restrict__ B,
                                              const float* __restrict__ R,
                                              float* __restrict__ C,
                                              int N, int K) {
    __shared__ float As[16][68], Bs[16][68];
    int m0 = blockIdx.y << 6, n0 = blockIdx.x << 6;
    int tid = threadIdx.x;
    int lr = tid >> 2, lk = (tid & 3) << 2;
    int ty = tid >> 4, tx = tid & 15;
    const float* Ap  = A + (size_t)(m0 + lr) * K + lk;
    const float* A2p = (EPI & 4) ? (A2 + (size_t)(m0 + lr) * K + lk) : A;
    const float* Bp  = B + (size_t)(n0 + lr) * K + lk;
    float acc[4][4];
    #pragma unroll
    for (int i = 0; i < 4; i++)
        #pragma unroll
        for (int j = 0; j < 4; j++) acc[i][j] = 0.0f;

    for (int k0 = 0; k0 < K; k0 += 16) {
        float4 a = *(const float4*)(Ap + k0);
        if (EPI & 4) {
            float4 a2 = *(const float4*)(A2p + k0);
            a.x *= a2.x; a.y *= a2.y; a.z *= a2.z; a.w *= a2.w;
        }
        float4 b = *(const float4*)(Bp + k0);
        As[lk+0][lr] = a.x; As[lk+1][lr] = a.y; As[lk+2][lr] = a.z; As[lk+3][lr] = a.w;
        Bs[lk+0][lr] = b.x; Bs[lk+1][lr] = b.y; Bs[lk+2][lr] = b.z; Bs[lk+3][lr] = b.w;
        __syncthreads();
        #pragma unroll
        for (int kk = 0; kk < 16; kk++) {
            float4 a4 = *(const float4*)(&As[kk][ty << 2]);
            float4 b4 = *(const float4*)(&Bs[kk][tx << 2]);
            float ar[4] = {a4.x, a4.y, a4.z, a4.w};
            float br[4] = {b4.x, b4.y, b4.z, b4.w};
            #pragma unroll
            for (int i = 0; i < 4; i++)
                #pragma unroll
                for (int j = 0; j < 4; j++)
                    acc[i][j] = fmaf(ar[i], br[j], acc[i][j]);
        }
        __syncthreads();
    }
    #pragma unroll
    for (int i = 0; i < 4; i++) {
        int row = m0 + (ty << 2) + i;
        float4 o; o.x = acc[i][0]; o.y = acc[i][1]; o.z = acc[i][2]; o.w = acc[i][3];
        if (EPI & 2) { o.x = gelu_exact(o.x); o.y = gelu_exact(o.y);
                       o.z = gelu_exact(o.z); o.w = gelu_exact(o.w); }
        if (EPI & 1) {
            float4 rv = *(const float4*)(R + (size_t)row * N + n0 + (tx << 2));
            o.x += rv.x; o.y += rv.y; o.z += rv.z; o.w += rv.w;
        }
        *(float4*)(C + (size_t)row * N + n0 + (tx << 2)) = o;
    }
}

// ---------------- scan dual-GEMM: z = left@P1^T + q@P2^T ----------------
__global__ void __launch_bounds__(256) gemm_scan(const float* __restrict__ q,
                                                 const float* __restrict__ P1,
                                                 const float* __restrict__ P2,
                                                 float* __restrict__ z, int d) {
    int m0 = blockIdx.y << 6, n0 = blockIdx.x << 6;
    int t0 = m0 & (TT - 1);
    if (t0 + 63 < d) return;  // whole block below frontier: rows just get copied later
    __shared__ float Al[16][68], Aq[16][68], B1[16][68], B2[16][68];
    int tid = threadIdx.x;
    int lr = tid >> 2, lk = (tid & 3) << 2;
    int ty = tid >> 4, tx = tid & 15;
    int r = m0 + lr;
    int t = r & (TT - 1);
    const float* aq = q + (size_t)r * CC + lk;
    const float* al = (t >= d) ? (aq - (size_t)d * CC) : aq;  // t<d rows are discarded later
    const float* b1 = P1 + (size_t)(n0 + lr) * CC + lk;
    const float* b2 = P2 + (size_t)(n0 + lr) * CC + lk;
    float acc[4][4];
    #pragma unroll
    for (int i = 0; i < 4; i++)
        #pragma unroll
        for (int j = 0; j < 4; j++) acc[i][j] = 0.0f;

    for (int k0 = 0; k0 < CC; k0 += 16) {
        float4 va = *(const float4*)(al + k0);
        float4 vq = *(const float4*)(aq + k0);
        float4 v1 = *(const float4*)(b1 + k0);
        float4 v2 = *(const float4*)(b2 + k0);
        Al[lk+0][lr] = va.x; Al[lk+1][lr] = va.y; Al[lk+2][lr] = va.z; Al[lk+3][lr] = va.w;
        Aq[lk+0][lr] = vq.x; Aq[lk+1][lr] = vq.y; Aq[lk+2][lr] = vq.z; Aq[lk+3][lr] = vq.w;
        B1[lk+0][lr] = v1.x; B1[lk+1][lr] = v1.y; B1[lk+2][lr] = v1.z; B1[lk+3][lr] = v1.w;
        B2[lk+0][lr] = v2.x; B2[lk+1][lr] = v2.y; B2[lk+2][lr] = v2.z; B2[lk+3][lr] = v2.w;
        __syncthreads();
        #pragma unroll
        for (int kk = 0; kk < 16; kk++) {
            float4 a4 = *(const float4*)(&Al[kk][ty << 2]);
            float4 q4 = *(const float4*)(&Aq[kk][ty << 2]);
            float4 x4 = *(const float4*)(&B1[kk][tx << 2]);
            float4 y4 = *(const float4*)(&B2[kk][tx << 2]);
            float ar[4] = {a4.x, a4.y, a4.z, a4.w};
            float qr[4] = {q4.x, q4.y, q4.z, q4.w};
            float b1r[4] = {x4.x, x4.y, x4.z, x4.w};
            float b2r[4] = {y4.x, y4.y, y4.z, y4.w};
            #pragma unroll
            for (int i = 0; i < 4; i++)
                #pragma unroll
                for (int j = 0; j < 4; j++) {
                    acc[i][j] = fmaf(ar[i], b1r[j], acc[i][j]);
                    acc[i][j] = fmaf(qr[i], b2r[j], acc[i][j]);
                }
        }
        __syncthreads();
    }
    #pragma unroll
    for (int i = 0; i < 4; i++) {
        int row = m0 + (ty << 2) + i;
        float4 o; o.x = acc[i][0]; o.y = acc[i][1]; o.z = acc[i][2]; o.w = acc[i][3];
        *(float4*)(z + (size_t)row * CC + n0 + (tx << 2)) = o;
    }
}

// ---------------- 512x512 small GEMM for polar iterations ----------------
// BT=true : C = alpha*(A@B^T) + beta*D     (NT)
// BT=false: C = alpha*(A@B)   + beta*D     (NN)
template<bool BT, bool AXPBY>
__global__ void __launch_bounds__(64) gemm512k(const float* __restrict__ A,
                                               const float* __restrict__ B,
                                               const float* __restrict__ D,
                                               float* __restrict__ C,
                                               float alpha, float beta) {
    size_t off = (size_t)blockIdx.z * CC * CC;
    A += off; B += off; C += off;
    if (AXPBY) D += off;
    int m0 = blockIdx.y << 5, n0 = blockIdx.x << 5;
    __shared__ float As[16][36], Bs[16][36];
    int tid = threadIdx.x;
    int ty = tid >> 3, tx = tid & 7;
    float acc[4][4];
    #pragma unroll
    for (int i = 0; i < 4; i++)
        #pragma unroll
        for (int j = 0; j < 4; j++) acc[i][j] = 0.0f;

    for (int k0 = 0; k0 < CC; k0 += 16) {
        #pragma unroll
        for (int u = 0; u < 2; u++) {
            int f = tid * 2 + u;
            int row = f >> 2, kq = (f & 3) << 2;
            float4 a = *(const float4*)(A + (size_t)(m0 + row) * CC + k0 + kq);
            As[kq+0][row] = a.x; As[kq+1][row] = a.y; As[kq+2][row] = a.z; As[kq+3][row] = a.w;
            if (BT) {
                float4 b = *(const float4*)(B + (size_t)(n0 + row) * CC + k0 + kq);
                Bs[kq+0][row] = b.x; Bs[kq+1][row] = b.y; Bs[kq+2][row] = b.z; Bs[kq+3][row] = b.w;
            } else {
                int krow = f >> 3, nf = f & 7;
                float4 b = *(const float4*)(B + (size_t)(k0 + krow) * CC + n0 + (nf << 2));
                *(float4*)(&Bs[krow][nf << 2]) = b;
            }
        }
        __syncthreads();
        #pragma unroll
        for (int kk = 0; kk < 16; kk++) {
            float4 a4 = *(const float4*)(&As[kk][ty << 2]);
            float4 b4 = *(const float4*)(&Bs[kk][tx << 2]);
            float ar[4] = {a4.x, a4.y, a4.z, a4.w};
            float br[4] = {b4.x, b4.y, b4.z, b4.w};
            #pragma unroll
            for (int i = 0; i < 4; i++)
                #pragma unroll
                for (int j = 0; j < 4; j++)
                    acc[i][j] = fmaf(ar[i], br[j], acc[i][j]);
        }
        __syncthreads();
    }
    #pragma unroll
    for (int i = 0; i < 4; i++) {
        int row = m0 + (ty << 2) + i;
        float4 o; o.x = acc[i][0]; o.y = acc[i][1]; o.z = acc[i][2]; o.w = acc[i][3];
        if (AXPBY) {
            float4 dv = *(const float4*)(D + (size_t)row * CC + n0 + (tx << 2));
            o.x = alpha * o.x + beta * dv.x;
            o.y = alpha * o.y + beta * dv.y;
            o.z = alpha * o.z + beta * dv.z;
            o.w = alpha * o.w + beta * dv.w;
        }
        *(float4*)(C + (size_t)row * CC + n0 + (tx << 2)) = o;
    }
}

// ---------------- polar init: Frobenius norm + scale ----------------
__global__ void fro_zero() { if (threadIdx.x < 2) g_n2[threadIdx.x] = 0.0f; }

__global__ void fro_reduce(const float* __restrict__ W1, const float* __restrict__ W2) {
    const float* W = blockIdx.y ? W2 : W1;
    int i = blockIdx.x * 256 + threadIdx.x;
    float s = 0.0f;
    for (int j = i; j < CC * CC; j += 64 * 256) { float v = W[j]; s += v * v; }
    #pragma unroll
    for (int o = 16; o; o >>= 1) s += __shfl_down_sync(0xffffffffu, s, o);
    __shared__ float sm[8];
    if ((threadIdx.x & 31) == 0) sm[threadIdx.x >> 5] = s;
    __syncthreads();
    if (threadIdx.x == 0) {
        float S = 0.0f;
        #pragma unroll
        for (int w = 0; w < 8; w++) S += sm[w];
        atomicAdd(&g_n2[blockIdx.y], S);
    }
}

__global__ void polar_init(const float* __restrict__ W1, const float* __restrict__ W2,
                           float* __restrict__ X) {
    int zb = blockIdx.y;
    const float* W = zb ? W2 : W1;
    float inv = rsqrtf(g_n2[zb]);
    int i = blockIdx.x * 256 + threadIdx.x;
    X[(size_t)zb * CC * CC + i] = W[i] * inv;
}

// ---------------- host orchestration ----------------
extern "C" void kernel_launch(void* const* d_in, const int* in_sizes, int n_in,
                              void* d_out, int out_size) {
    const float* x    = (const float*)d_in[0];
    const float* ln1w = (const float*)d_in[1];
    const float* Wq   = (const float*)d_in[2];
    const float* Wv   = (const float*)d_in[3];
    const float* Wo   = (const float*)d_in[4];
    // d_in[5] = identity : provably unused (pscan discards all rows that see it)
    const float* Wp1  = (const float*)d_in[6];
    const float* Wp2  = (const float*)d_in[7];
    const float* ln2w = (const float*)d_in[8];
    const float* Wfc  = (const float*)d_in[9];
    const float* Wpr  = (const float*)d_in[10];
    float* out = (float*)d_out;

    float *h, *q0, *q1, *v, *zb, *x1, *mlp, *pA, *pB, *pY, *pZ;
    cudaGetSymbolAddress((void**)&h,   g_h);
    cudaGetSymbolAddress((void**)&q0,  g_q0);
    cudaGetSymbolAddress((void**)&q1,  g_q1);
    cudaGetSymbolAddress((void**)&v,   g_v);
    cudaGetSymbolAddress((void**)&zb,  g_zb);
    cudaGetSymbolAddress((void**)&x1,  g_x1);
    cudaGetSymbolAddress((void**)&mlp, g_mlp);
    cudaGetSymbolAddress((void**)&pA,  g_pA);
    cudaGetSymbolAddress((void**)&pB,  g_pB);
    cudaGetSymbolAddress((void**)&pY,  g_pY);
    cudaGetSymbolAddress((void**)&pZ,  g_pZ);

    dim3 g8(8, 256), g32(32, 256);

    // --- SSM branch prologue ---
    ln_kernel<<<MT, 128>>>(x, ln1w, h);
    gemm64<0><<<g8, 256>>>(h, nullptr, Wq, nullptr, q0, 512, 512);
    gemm64<0><<<g8, 256>>>(h, nullptr, Wv, nullptr, v,  512, 512);

    // --- polar factors of Wp1, Wp2 via quintic + Newton-Schulz ---
    fro_zero<<<1, 32>>>();
    fro_reduce<<<dim3(64, 2), 256>>>(Wp1, Wp2);
    polar_init<<<dim3(1024, 2), 256>>>(Wp1, Wp2, pA);

    float* X  = pA;
    float* Xn = pB;
    dim3 gs(16, 16, 2);
    const float qa = 3.4445f, qb = -4.7750f, qc = 2.0315f;
    for (int it = 0; it < 12; it++) {
        gemm512k<true,  false><<<gs, 64>>>(X,  X,  nullptr, pY, 1.0f, 0.0f);  // Y = X X^T
        gemm512k<true,  true ><<<gs, 64>>>(pY, pY, pY,      pZ, qc,   qb);    // Z = c Y^2 + b Y
        gemm512k<false, true ><<<gs, 64>>>(pZ, X,  X,       Xn, 1.0f, qa);    // X' = Z X + a X
        float* t = X; X = Xn; Xn = t;
    }
    for (int it = 0; it < 6; it++) {
        gemm512k<true,  false><<<gs, 64>>>(X,  X, nullptr, pY, 1.0f,  0.0f);  // Y = X X^T
        gemm512k<false, true ><<<gs, 64>>>(pY, X, X,       Xn, -0.5f, 1.5f);  // X' = 1.5X - .5 Y X
        float* t = X; X = Xn; Xn = t;
    }
    const float* P1 = X;
    const float* P2 = X + CC * CC;

    // --- parallel scan: 12 levels ---
    float* qc_ = q0;
    float* qn_ = q1;
    for (int d = 1; d < TT; d <<= 1) {
        gemm_scan<<<g8, 256>>>(qc_, P1, P2, zb, d);
        rms_update<<<MT, 128>>>(zb, qc_, qn_, d);
        float* t = qc_; qc_ = qn_; qn_ = t;
    }

    // --- output projection: x1 = x + (q*v) @ Wo^T ---
    gemm64<5><<<g8, 256>>>(qc_, v, Wo, x, x1, 512, 512);

    // --- MLP branch ---
    ln_kernel<<<MT, 128>>>(x1, ln2w, h);
    gemm64<2><<<g32, 256>>>(h,   nullptr, Wfc, nullptr, mlp, 2048, 512);   // gelu(h @ Wfc^T)
    gemm64<1><<<g8,  256>>>(mlp, nullptr, Wpr, x1,      out, 512, 2048);   // out = x1 + mlp @ Wpr^T
}

// round 4
// speedup vs baseline: 1.6781x; 1.6755x over previous
#include <cuda_runtime.h>
#include <cuda_bf16.h>
#include <math.h>
#include <stdint.h>

#define MT 16384   // B*T
#define TT 4096
#define CC 512

// ---------------- scratch (device globals; no runtime allocation) ----------------
__device__ float g_h  [MT*CC];
__device__ float g_q0 [MT*CC];
__device__ float g_q1 [MT*CC];
__device__ float g_v  [MT*CC];
__device__ float g_zb [MT*CC];
__device__ float g_x1 [MT*CC];
__device__ float g_mlp[MT*2048];
__device__ float g_pA [2*CC*CC];
__device__ float g_pB [2*CC*CC];
__device__ float g_pY [2*CC*CC];
__device__ float g_pZ [2*CC*CC];
__device__ float g_n2 [2];

// ================= bf16 split-3 mma.sync GEMM machinery =================
// smem buffer: 4 tiles (Ahi, Alo, Bhi, Blo), each 128 rows x 32 bf16, row stride 80B
#define ROWB    80
#define OFF_AHI 0
#define OFF_ALO 10240
#define OFF_BHI 20480
#define OFF_BLO 30720
#define BUFSTR  40960
#define SMB     (2*BUFSTR)

__device__ __forceinline__ void mma_bf16(float c[4], const uint32_t a[4], const uint32_t b[2]) {
    asm volatile("mma.sync.aligned.m16n8k16.row.col.f32.bf16.bf16.f32 "
                 "{%0,%1,%2,%3}, {%4,%5,%6,%7}, {%8,%9}, {%0,%1,%2,%3};"
                 : "+f"(c[0]), "+f"(c[1]), "+f"(c[2]), "+f"(c[3])
                 : "r"(a[0]), "r"(a[1]), "r"(a[2]), "r"(a[3]), "r"(b[0]), "r"(b[1]));
}

// f32x4 -> (hi,lo) bf16 pairs, stored at row-stride-80 layout
__device__ __forceinline__ void cvt_store4(float4 v, char* hib, char* lob, int row, int colbf) {
    int off = row * ROWB + colbf * 2;
    __nv_bfloat16 h0 = __float2bfloat16(v.x), h1 = __float2bfloat16(v.y);
    __nv_bfloat16 h2 = __float2bfloat16(v.z), h3 = __float2bfloat16(v.w);
    float r0 = v.x - __bfloat162float(h0), r1 = v.y - __bfloat162float(h1);
    float r2 = v.z - __bfloat162float(h2), r3 = v.w - __bfloat162float(h3);
    __nv_bfloat162 ph0 = __halves2bfloat162(h0, h1), ph1 = __halves2bfloat162(h2, h3);
    __nv_bfloat162 pl0 = __halves2bfloat162(__float2bfloat16(r0), __float2bfloat16(r1));
    __nv_bfloat162 pl1 = __halves2bfloat162(__float2bfloat16(r2), __float2bfloat16(r3));
    uint2 hw, lw;
    hw.x = *reinterpret_cast<uint32_t*>(&ph0); hw.y = *reinterpret_cast<uint32_t*>(&ph1);
    lw.x = *reinterpret_cast<uint32_t*>(&pl0); lw.y = *reinterpret_cast<uint32_t*>(&pl1);
    *reinterpret_cast<uint2*>(hib + off) = hw;
    *reinterpret_cast<uint2*>(lob + off) = lw;
}

__device__ __forceinline__ uint32_t ld32s(const char* b, int row, int colbf) {
    return *reinterpret_cast<const uint32_t*>(b + row * ROWB + colbf * 2);
}

// per-warp compute of one K=32 chunk (split-3)
__device__ __forceinline__ void compute_chunk(const char* buf, float acc[2][8][4],
                                              int mw, int nw, int g, int tg) {
    #pragma unroll
    for (int ks = 0; ks < 2; ks++) {
        int kb = ks * 16 + 2 * tg;
        uint32_t ah[2][4], al[2][4];
        #pragma unroll
        for (int mt = 0; mt < 2; mt++) {
            int r = mw + mt * 16 + g;
            ah[mt][0] = ld32s(buf + OFF_AHI, r,     kb);
            ah[mt][1] = ld32s(buf + OFF_AHI, r + 8, kb);
            ah[mt][2] = ld32s(buf + OFF_AHI, r,     kb + 8);
            ah[mt][3] = ld32s(buf + OFF_AHI, r + 8, kb + 8);
            al[mt][0] = ld32s(buf + OFF_ALO, r,     kb);
            al[mt][1] = ld32s(buf + OFF_ALO, r + 8, kb);
            al[mt][2] = ld32s(buf + OFF_ALO, r,     kb + 8);
            al[mt][3] = ld32s(buf + OFF_ALO, r + 8, kb + 8);
        }
        #pragma unroll
        for (int nt = 0; nt < 8; nt++) {
            int rn = nw + nt * 8 + g;
            uint32_t bh[2], bl[2];
            bh[0] = ld32s(buf + OFF_BHI, rn, kb);
            bh[1] = ld32s(buf + OFF_BHI, rn, kb + 8);
            bl[0] = ld32s(buf + OFF_BLO, rn, kb);
            bl[1] = ld32s(buf + OFF_BLO, rn, kb + 8);
            #pragma unroll
            for (int mt = 0; mt < 2; mt++) {
                mma_bf16(acc[mt][nt], ah[mt], bh);
                mma_bf16(acc[mt][nt], ah[mt], bl);
                mma_bf16(acc[mt][nt], al[mt], bh);
            }
        }
    }
}

__device__ __forceinline__ float gelu_exact(float v) {
    return 0.5f * v * (1.0f + erff(v * 0.7071067811865475f));
}

// ================= generic tensor GEMM: C = A@B^T (+R) (gelu) (A:=A*A2) =================
// EPI bit0 = residual R, bit1 = gelu, bit2 = A elementwise * A2
template<int EPI>
__global__ void __launch_bounds__(256) tgemm(const float* __restrict__ A,
                                             const float* __restrict__ A2,
                                             const float* __restrict__ B,
                                             const float* __restrict__ R,
                                             float* __restrict__ C,
                                             int N, int K) {
    extern __shared__ __align__(16) char smem[];
    int tid = threadIdx.x, wid = tid >> 5, lane = tid & 31;
    int g = lane >> 2, tg = lane & 3;
    int m0 = blockIdx.y << 7, n0 = blockIdx.x << 7;
    int mw = (wid >> 1) << 5, nw = (wid & 1) << 6;

    int lr = tid >> 1, lc = (tid & 1) << 4;          // staging: row 0..127, col 0/16
    const float* Ap  = A + (size_t)(m0 + lr) * K + lc;
    const float* A2p = (EPI & 4) ? (A2 + (size_t)(m0 + lr) * K + lc) : Ap;
    const float* Bp  = B + (size_t)(n0 + lr) * K + lc;

    float acc[2][8][4];
    #pragma unroll
    for (int mt = 0; mt < 2; mt++)
        #pragma unroll
        for (int nt = 0; nt < 8; nt++)
            #pragma unroll
            for (int j = 0; j < 4; j++) acc[mt][nt][j] = 0.0f;

    int nch = K >> 5;
    float4 ra[4], rb[4];
    // prologue: stage chunk 0
    #pragma unroll
    for (int i = 0; i < 4; i++) {
        ra[i] = *(const float4*)(Ap + i * 4);
        if (EPI & 4) {
            float4 w = *(const float4*)(A2p + i * 4);
            ra[i].x *= w.x; ra[i].y *= w.y; ra[i].z *= w.z; ra[i].w *= w.w;
        }
        rb[i] = *(const float4*)(Bp + i * 4);
    }
    #pragma unroll
    for (int i = 0; i < 4; i++) {
        cvt_store4(ra[i], smem + OFF_AHI, smem + OFF_ALO, lr, lc + i * 4);
        cvt_store4(rb[i], smem + OFF_BHI, smem + OFF_BLO, lr, lc + i * 4);
    }
    __syncthreads();

    for (int c = 0; c < nch; c++) {
        if (c + 1 < nch) {
            int k0 = (c + 1) << 5;
            #pragma unroll
            for (int i = 0; i < 4; i++) {
                ra[i] = *(const float4*)(Ap + k0 + i * 4);
                if (EPI & 4) {
                    float4 w = *(const float4*)(A2p + k0 + i * 4);
                    ra[i].x *= w.x; ra[i].y *= w.y; ra[i].z *= w.z; ra[i].w *= w.w;
                }
                rb[i] = *(const float4*)(Bp + k0 + i * 4);
            }
        }
        compute_chunk(smem + (c & 1) * BUFSTR, acc, mw, nw, g, tg);
        if (c + 1 < nch) {
            char* nb = smem + ((c + 1) & 1) * BUFSTR;
            #pragma unroll
            for (int i = 0; i < 4; i++) {
                cvt_store4(ra[i], nb + OFF_AHI, nb + OFF_ALO, lr, lc + i * 4);
                cvt_store4(rb[i], nb + OFF_BHI, nb + OFF_BLO, lr, lc + i * 4);
            }
        }
        __syncthreads();
    }

    // epilogue: fragment layout -> C
    #pragma unroll
    for (int mt = 0; mt < 2; mt++) {
        #pragma unroll
        for (int nt = 0; nt < 8; nt++) {
            int row = m0 + mw + mt * 16 + g;
            int col = n0 + nw + nt * 8 + 2 * tg;
            #pragma unroll
            for (int hh = 0; hh < 2; hh++) {
                int rr = row + hh * 8;
                float2 o;
                o.x = acc[mt][nt][hh * 2 + 0];
                o.y = acc[mt][nt][hh * 2 + 1];
                if (EPI & 2) { o.x = gelu_exact(o.x); o.y = gelu_exact(o.y); }
                if (EPI & 1) {
                    float2 rv = *(const float2*)(R + (size_t)rr * N + col);
                    o.x += rv.x; o.y += rv.y;
                }
                *(float2*)(C + (size_t)rr * N + col) = o;
            }
        }
    }
}

// ================= scan dual-GEMM: z = left@P1^T + q@P2^T (fused K=1024) =================
__global__ void __launch_bounds__(256) tscan(const float* __restrict__ q,
                                             const float* __restrict__ P1,
                                             const float* __restrict__ P2,
                                             float* __restrict__ z, int d) {
    int m0 = blockIdx.y << 7, n0 = blockIdx.x << 7;
    if ((m0 & (TT - 1)) + 127 < d) return;  // fully below frontier: rows copied later
    extern __shared__ __align__(16) char smem[];
    int tid = threadIdx.x, wid = tid >> 5, lane = tid & 31;
    int g = lane >> 2, tg = lane & 3;
    int mw = (wid >> 1) << 5, nw = (wid & 1) << 6;

    int lr = tid >> 1, lc = (tid & 1) << 4;
    int gr = m0 + lr;
    int t  = gr & (TT - 1);
    int grL = (t >= d) ? gr - d : gr;   // rows with t<d discarded by rms_update
    const float* AqL = q + (size_t)grL * CC + lc;
    const float* Aq  = q + (size_t)gr  * CC + lc;
    const float* B1p = P1 + (size_t)(n0 + lr) * CC + lc;
    const float* B2p = P2 + (size_t)(n0 + lr) * CC + lc;

    float acc[2][8][4];
    #pragma unroll
    for (int mt = 0; mt < 2; mt++)
        #pragma unroll
        for (int nt = 0; nt < 8; nt++)
            #pragma unroll
            for (int j = 0; j < 4; j++) acc[mt][nt][j] = 0.0f;

    float4 ra[4], rb[4];
    #pragma unroll
    for (int i = 0; i < 4; i++) {
        ra[i] = *(const float4*)(AqL + i * 4);
        rb[i] = *(const float4*)(B1p + i * 4);
    }
    #pragma unroll
    for (int i = 0; i < 4; i++) {
        cvt_store4(ra[i], smem + OFF_AHI, smem + OFF_ALO, lr, lc + i * 4);
        cvt_store4(rb[i], smem + OFF_BHI, smem + OFF_BLO, lr, lc + i * 4);
    }
    __syncthreads();

    for (int c = 0; c < 32; c++) {
        if (c + 1 < 32) {
            int cn = c + 1;
            int k0 = (cn & 15) << 5;
            const float* ap = (cn < 16) ? AqL : Aq;
            const float* bp = (cn < 16) ? B1p : B2p;
            #pragma unroll
            for (int i = 0; i < 4; i++) {
                ra[i] = *(const float4*)(ap + k0 + i * 4);
                rb[i] = *(const float4*)(bp + k0 + i * 4);
            }
        }
        compute_chunk(smem + (c & 1) * BUFSTR, acc, mw, nw, g, tg);
        if (c + 1 < 32) {
            char* nb = smem + ((c + 1) & 1) * BUFSTR;
            #pragma unroll
            for (int i = 0; i < 4; i++) {
                cvt_store4(ra[i], nb + OFF_AHI, nb + OFF_ALO, lr, lc + i * 4);
                cvt_store4(rb[i], nb + OFF_BHI, nb + OFF_BLO, lr, lc + i * 4);
            }
        }
        __syncthreads();
    }

    #pragma unroll
    for (int mt = 0; mt < 2; mt++) {
        #pragma unroll
        for (int nt = 0; nt < 8; nt++) {
            int row = m0 + mw + mt * 16 + g;
            int col = n0 + nw + nt * 8 + 2 * tg;
            #pragma unroll
            for (int hh = 0; hh < 2; hh++) {
                int rr = row + hh * 8;
                float2 o;
                o.x = acc[mt][nt][hh * 2 + 0];
                o.y = acc[mt][nt][hh * 2 + 1];
                *(float2*)(z + (size_t)rr * CC + col) = o;
            }
        }
    }
}

// ---------------- layernorm (one block per row, 128 threads) ----------------
__global__ void ln_kernel(const float* __restrict__ x, const float* __restrict__ w,
                          float* __restrict__ out) {
    int r = blockIdx.x;
    const float4* xr = (const float4*)(x + (size_t)r * CC);
    float4 v = xr[threadIdx.x];
    float s  = v.x + v.y + v.z + v.w;
    float s2 = v.x*v.x + v.y*v.y + v.z*v.z + v.w*v.w;
    __shared__ float sm[8];
    #pragma unroll
    for (int o = 16; o; o >>= 1) {
        s  += __shfl_down_sync(0xffffffffu, s,  o);
        s2 += __shfl_down_sync(0xffffffffu, s2, o);
    }
    if ((threadIdx.x & 31) == 0) { sm[threadIdx.x >> 5] = s; sm[(threadIdx.x >> 5) + 4] = s2; }
    __syncthreads();
    float S  = sm[0] + sm[1] + sm[2] + sm[3];
    float S2 = sm[4] + sm[5] + sm[6] + sm[7];
    float mean = S * (1.0f / CC);
    float var  = S2 * (1.0f / CC) - mean * mean;
    float rstd = rsqrtf(var + 1e-5f);
    float4 wv = ((const float4*)w)[threadIdx.x];
    float4 o;
    o.x = (v.x - mean) * rstd * wv.x;
    o.y = (v.y - mean) * rstd * wv.y;
    o.z = (v.z - mean) * rstd * wv.z;
    o.w = (v.w - mean) * rstd * wv.w;
    ((float4*)(out + (size_t)r * CC))[threadIdx.x] = o;
}

// ---------------- rmsnorm + frontier select for the scan ----------------
__global__ void rms_update(const float* __restrict__ z, const float* __restrict__ qin,
                           float* __restrict__ qout, int d) {
    int r = blockIdx.x;
    int t = r & (TT - 1);
    if (t >= d) {
        float4 v = ((const float4*)(z + (size_t)r * CC))[threadIdx.x];
        float s2 = v.x*v.x + v.y*v.y + v.z*v.z + v.w*v.w;
        __shared__ float sm[4];
        #pragma unroll
        for (int o = 16; o; o >>= 1) s2 += __shfl_down_sync(0xffffffffu, s2, o);
        if ((threadIdx.x & 31) == 0) sm[threadIdx.x >> 5] = s2;
        __syncthreads();
        float S2 = sm[0] + sm[1] + sm[2] + sm[3];
        float sc = rsqrtf(S2 * (1.0f / CC) + 1e-6f);
        float4 o; o.x = v.x*sc; o.y = v.y*sc; o.z = v.z*sc; o.w = v.w*sc;
        ((float4*)(qout + (size_t)r * CC))[threadIdx.x] = o;
    } else {
        ((float4*)(qout + (size_t)r * CC))[threadIdx.x] =
            ((const float4*)(qin + (size_t)r * CC))[threadIdx.x];
    }
}

// ---------------- 512x512 small GEMM for polar iterations (fp32 SIMT) ----------------
template<bool BT, bool AXPBY>
__global__ void __launch_bounds__(64) gemm512k(const float* __restrict__ A,
                                               const float* __restrict__ B,
                                               const float* __restrict__ D,
                                               float* __restrict__ C,
                                               float alpha, float beta) {
    size_t off = (size_t)blockIdx.z * CC * CC;
    A += off; B += off; C += off;
    if (AXPBY) D += off;
    int m0 = blockIdx.y << 5, n0 = blockIdx.x << 5;
    __shared__ float As[16][36], Bs[16][36];
    int tid = threadIdx.x;
    int ty = tid >> 3, tx = tid & 7;
    float acc[4][4];
    #pragma unroll
    for (int i = 0; i < 4; i++)
        #pragma unroll
        for (int j = 0; j < 4; j++) acc[i][j] = 0.0f;

    for (int k0 = 0; k0 < CC; k0 += 16) {
        #pragma unroll
        for (int u = 0; u < 2; u++) {
            int f = tid * 2 + u;
            int row = f >> 2, kq = (f & 3) << 2;
            float4 a = *(const float4*)(A + (size_t)(m0 + row) * CC + k0 + kq);
            As[kq+0][row] = a.x; As[kq+1][row] = a.y; As[kq+2][row] = a.z; As[kq+3][row] = a.w;
            if (BT) {
                float4 b = *(const float4*)(B + (size_t)(n0 + row) * CC + k0 + kq);
                Bs[kq+0][row] = b.x; Bs[kq+1][row] = b.y; Bs[kq+2][row] = b.z; Bs[kq+3][row] = b.w;
            } else {
                int krow = f >> 3, nf = f & 7;
                float4 b = *(const float4*)(B + (size_t)(k0 + krow) * CC + n0 + (nf << 2));
                *(float4*)(&Bs[krow][nf << 2]) = b;
            }
        }
        __syncthreads();
        #pragma unroll
        for (int kk = 0; kk < 16; kk++) {
            float4 a4 = *(const float4*)(&As[kk][ty << 2]);
            float4 b4 = *(const float4*)(&Bs[kk][tx << 2]);
            float ar[4] = {a4.x, a4.y, a4.z, a4.w};
            float br[4] = {b4.x, b4.y, b4.z, b4.w};
            #pragma unroll
            for (int i = 0; i < 4; i++)
                #pragma unroll
                for (int j = 0; j < 4; j++)
                    acc[i][j] = fmaf(ar[i], br[j], acc[i][j]);
        }
        __syncthreads();
    }
    #pragma unroll
    for (int i = 0; i < 4; i++) {
        int row = m0 + (ty << 2) + i;
        float4 o; o.x = acc[i][0]; o.y = acc[i][1]; o.z = acc[i][2]; o.w = acc[i][3];
        if (AXPBY) {
            float4 dv = *(const float4*)(D + (size_t)row * CC + n0 + (tx << 2));
            o.x = alpha * o.x + beta * dv.x;
            o.y = alpha * o.y + beta * dv.y;
            o.z = alpha * o.z + beta * dv.z;
            o.w = alpha * o.w + beta * dv.w;
        }
        *(float4*)(C + (size_t)row * CC + n0 + (tx << 2)) = o;
    }
}

// ---------------- polar init: Frobenius norm + scale ----------------
__global__ void fro_zero() { if (threadIdx.x < 2) g_n2[threadIdx.x] = 0.0f; }

__global__ void fro_reduce(const float* __restrict__ W1, const float* __restrict__ W2) {
    const float* W = blockIdx.y ? W2 : W1;
    int i = blockIdx.x * 256 + threadIdx.x;
    float s = 0.0f;
    for (int j = i; j < CC * CC; j += 64 * 256) { float v = W[j]; s += v * v; }
    #pragma unroll
    for (int o = 16; o; o >>= 1) s += __shfl_down_sync(0xffffffffu, s, o);
    __shared__ float sm[8];
    if ((threadIdx.x & 31) == 0) sm[threadIdx.x >> 5] = s;
    __syncthreads();
    if (threadIdx.x == 0) {
        float S = 0.0f;
        #pragma unroll
        for (int w = 0; w < 8; w++) S += sm[w];
        atomicAdd(&g_n2[blockIdx.y], S);
    }
}

__global__ void polar_init(const float* __restrict__ W1, const float* __restrict__ W2,
                           float* __restrict__ X) {
    int zb = blockIdx.y;
    const float* W = zb ? W2 : W1;
    float inv = rsqrtf(g_n2[zb]);
    int i = blockIdx.x * 256 + threadIdx.x;
    X[(size_t)zb * CC * CC + i] = W[i] * inv;
}

// ---------------- host orchestration ----------------
extern "C" void kernel_launch(void* const* d_in, const int* in_sizes, int n_in,
                              void* d_out, int out_size) {
    const float* x    = (const float*)d_in[0];
    const float* ln1w = (const float*)d_in[1];
    const float* Wq   = (const float*)d_in[2];
    const float* Wv   = (const float*)d_in[3];
    const float* Wo   = (const float*)d_in[4];
    // d_in[5] = identity : provably unused (pscan discards all rows that see it)
    const float* Wp1  = (const float*)d_in[6];
    const float* Wp2  = (const float*)d_in[7];
    const float* ln2w = (const float*)d_in[8];
    const float* Wfc  = (const float*)d_in[9];
    const float* Wpr  = (const float*)d_in[10];
    float* out = (float*)d_out;

    float *h, *q0, *q1, *v, *zb, *x1, *mlp, *pA, *pB, *pY, *pZ;
    cudaGetSymbolAddress((void**)&h,   g_h);
    cudaGetSymbolAddress((void**)&q0,  g_q0);
    cudaGetSymbolAddress((void**)&q1,  g_q1);
    cudaGetSymbolAddress((void**)&v,   g_v);
    cudaGetSymbolAddress((void**)&zb,  g_zb);
    cudaGetSymbolAddress((void**)&x1,  g_x1);
    cudaGetSymbolAddress((void**)&mlp, g_mlp);
    cudaGetSymbolAddress((void**)&pA,  g_pA);
    cudaGetSymbolAddress((void**)&pB,  g_pB);
    cudaGetSymbolAddress((void**)&pY,  g_pY);
    cudaGetSymbolAddress((void**)&pZ,  g_pZ);

    cudaFuncSetAttribute(tgemm<0>, cudaFuncAttributeMaxDynamicSharedMemorySize, SMB);
    cudaFuncSetAttribute(tgemm<1>, cudaFuncAttributeMaxDynamicSharedMemorySize, SMB);
    cudaFuncSetAttribute(tgemm<2>, cudaFuncAttributeMaxDynamicSharedMemorySize, SMB);
    cudaFuncSetAttribute(tgemm<5>, cudaFuncAttributeMaxDynamicSharedMemorySize, SMB);
    cudaFuncSetAttribute(tscan,    cudaFuncAttributeMaxDynamicSharedMemorySize, SMB);

    dim3 gQ(4, 128);    // N=512 tiles of 128
    dim3 gF(16, 128);   // N=2048

    // --- SSM branch prologue ---
    ln_kernel<<<MT, 128>>>(x, ln1w, h);
    tgemm<0><<<gQ, 256, SMB>>>(h, nullptr, Wq, nullptr, q0, 512, 512);
    tgemm<0><<<gQ, 256, SMB>>>(h, nullptr, Wv, nullptr, v,  512, 512);

    // --- polar factors of Wp1, Wp2 via quintic + Newton-Schulz (fp32 SIMT) ---
    fro_zero<<<1, 32>>>();
    fro_reduce<<<dim3(64, 2), 256>>>(Wp1, Wp2);
    polar_init<<<dim3(1024, 2), 256>>>(Wp1, Wp2, pA);

    float* X  = pA;
    float* Xn = pB;
    dim3 gs(16, 16, 2);
    const float qa = 3.4445f, qb = -4.7750f, qc = 2.0315f;
    for (int it = 0; it < 12; it++) {
        gemm512k<true,  false><<<gs, 64>>>(X,  X,  nullptr, pY, 1.0f, 0.0f);  // Y = X X^T
        gemm512k<true,  true ><<<gs, 64>>>(pY, pY, pY,      pZ, qc,   qb);    // Z = c Y^2 + b Y
        gemm512k<false, true ><<<gs, 64>>>(pZ, X,  X,       Xn, 1.0f, qa);    // X' = Z X + a X
        float* t = X; X = Xn; Xn = t;
    }
    for (int it = 0; it < 6; it++) {
        gemm512k<true,  false><<<gs, 64>>>(X,  X, nullptr, pY, 1.0f,  0.0f);  // Y = X X^T
        gemm512k<false, true ><<<gs, 64>>>(pY, X, X,       Xn, -0.5f, 1.5f);  // X' = 1.5X - .5 Y X
        float* t = X; X = Xn; Xn = t;
    }
    const float* P1 = X;
    const float* P2 = X + CC * CC;

    // --- parallel scan: 12 levels on tensor cores ---
    float* qc_ = q0;
    float* qn_ = q1;
    for (int d = 1; d < TT; d <<= 1) {
        tscan<<<gQ, 256, SMB>>>(qc_, P1, P2, zb, d);
        rms_update<<<MT, 128>>>(zb, qc_, qn_, d);
        float* t = qc_; qc_ = qn_; qn_ = t;
    }

    // --- output projection: x1 = x + (q*v) @ Wo^T ---
    tgemm<5><<<gQ, 256, SMB>>>(qc_, v, Wo, x, x1, 512, 512);

    // --- MLP branch ---
    ln_kernel<<<MT, 128>>>(x1, ln2w, h);
    tgemm<2><<<gF, 256, SMB>>>(h,   nullptr, Wfc, nullptr, mlp, 2048, 512);   // gelu(h @ Wfc^T)
    tgemm<1><<<gQ, 256, SMB>>>(mlp, nullptr, Wpr, x1,      out, 512, 2048);   // out = x1 + mlp @ Wpr^T
}